// round 1
// baseline (speedup 1.0000x reference)
#include <cuda_runtime.h>
#include <math.h>

#define T_LEN 8192
#define NT    512
#define EPT   (T_LEN / NT)      // 16
#define NWARP (NT / 32)         // 16

// ---------------- block reductions ----------------
__device__ __forceinline__ float blk_sum(float v, volatile float* red, int lane, int warp) {
    #pragma unroll
    for (int o = 16; o > 0; o >>= 1) v += __shfl_xor_sync(0xffffffffu, v, o);
    if (lane == 0) red[warp] = v;
    __syncthreads();
    float t = 0.f;
    #pragma unroll
    for (int w = 0; w < NWARP; w++) t += red[w];
    __syncthreads();
    return t;
}

__device__ __forceinline__ float blk_max(float v, volatile float* red, int lane, int warp) {
    #pragma unroll
    for (int o = 16; o > 0; o >>= 1) v = fmaxf(v, __shfl_xor_sync(0xffffffffu, v, o));
    if (lane == 0) red[warp] = v;
    __syncthreads();
    float t = red[0];
    #pragma unroll
    for (int w = 1; w < NWARP; w++) t = fmaxf(t, red[w]);
    __syncthreads();
    return t;
}

__device__ __forceinline__ int blk_cnt(int v, volatile int* red, int lane, int warp) {
    #pragma unroll
    for (int o = 16; o > 0; o >>= 1) v += __shfl_xor_sync(0xffffffffu, v, o);
    if (lane == 0) red[warp] = v;
    __syncthreads();
    int t = 0;
    #pragma unroll
    for (int w = 0; w < NWARP; w++) t += red[w];
    __syncthreads();
    return t;
}

// ---------------- main kernel: one CTA per batch row ----------------
__global__ __launch_bounds__(NT, 2)
void srp_kernel(const float* __restrict__ g_da,   // dur_anchor_src      [B,T]
                const float* __restrict__ g_lr,   // dur_logratio_unit   [B,T]
                const float* __restrict__ g_pw,   // pause_weight_unit   [B,T]
                const float* __restrict__ g_bl,   // boundary_latent     [B,T]
                const float* __restrict__ g_um,   // unit_mask           [B,T]
                const float* __restrict__ g_sbw,  // speech_budget_win   [B]
                const float* __restrict__ g_pbw,  // pause_budget_win    [B]
                const float* __restrict__ g_pse,  // previous_speech_exec[B,T]
                const float* __restrict__ g_ppe,  // previous_pause_exec [B,T]
                const int*   __restrict__ g_cf,   // commit_frontier     [B]
                float*       __restrict__ g_out,  // [2,B,T]
                int B, int keep_k)
{
    extern __shared__ float smem[];
    float* sm_um = smem;                // [T] unit_mask
    float* sm_av = smem + T_LEN;        // [T] prefix ? prev_speech : clip-candidate (no mask)
    float* sm_pb = smem + 2 * T_LEN;    // [T] prefix ? prev_pause  : 0
    __shared__ float redf[NWARP];
    __shared__ int   redi[NWARP];

    const int b    = blockIdx.x;
    const int tid  = threadIdx.x;
    const int lane = tid & 31;
    const int warp = tid >> 5;
    const size_t off = (size_t)b * T_LEN;

    const float* da  = g_da  + off;
    const float* lr  = g_lr  + off;
    const float* pw  = g_pw  + off;
    const float* bl  = g_bl  + off;
    const float* um  = g_um  + off;
    const float* pse = g_pse + off;
    const float* ppe = g_ppe + off;

    const int F = g_cf[b];

    // ---- phase 1: stream inputs once; reductions; cache per-element state ----
    float s_r[EPT];
    float a_ps = 0.f, a_pp = 0.f, a_tc = 0.f, a_cs = 0.f, a_mx = 0.f;

    #pragma unroll
    for (int j = 0; j < EPT; j++) {
        const int i = tid + j * NT;
        const float u      = __ldg(um + i);
        const float anchor = fmaxf(__ldg(da + i), 1.0f);
        const float c      = fminf(fmaxf(anchor * __expf(__ldg(lr + i)), 1.0f), anchor * 3.0f);
        const float sc     = (fmaxf(__ldg(pw + i), 0.f)
                              + 0.15f * (0.1f + fmaxf(__ldg(bl + i), 0.f))) * u;
        const bool  pf     = (i < F);
        const float tail   = pf ? 0.f : u;
        const float psv    = __ldg(pse + i);
        const float ppv    = __ldg(ppe + i);

        if (pf) { a_ps += psv * u; a_pp += ppv * u; }
        a_tc += tail;
        a_cs += c * u * tail;         // candidate * tail_mask
        a_mx  = fmaxf(a_mx, sc);
        s_r[j] = sc;

        sm_um[i] = u;                 // read back by the SAME thread -> no sync dependency
        sm_av[i] = pf ? psv : c;
        sm_pb[i] = pf ? ppv : 0.f;
    }

    const float ps  = blk_sum(a_ps, redf, lane, warp);
    const float pp  = blk_sum(a_pp, redf, lane, warp);
    const float tc  = blk_sum(a_tc, redf, lane, warp);
    const float cs  = blk_sum(a_cs, redf, lane, warp);
    const float smx = blk_max(a_mx, redf, lane, warp);

    // ---- per-row scalars (computed redundantly, identically, in every thread) ----
    const float sbud   = fmaxf(__ldg(g_sbw + b), ps + tc * 1.0f);   // MIN_SPEECH = 1.0
    const float pbud   = fmaxf(__ldg(g_pbw + b), pp);
    const float rem_s  = sbud - ps;
    const float cts    = fmaxf(cs, 1e-6f);
    const float scale_s = (tc > 0.f && rem_s > 0.f) ? (rem_s / cts) : 0.f;
    const float rem_p  = fmaxf(pbud - pp, 0.f);

    // ---- exact k-th-largest via bit bisection on register-resident scores ----
    int c0 = 0;
    #pragma unroll
    for (int j = 0; j < EPT; j++) c0 += (s_r[j] > 0.f);
    c0 = blk_cnt(c0, redi, lane, warp);

    float thr = 0.f;
    if (c0 >= keep_k) {
        // invariant: count(> float(lo)) >= k, count(> float(hi)) < k, v_k in (lo, hi]
        unsigned lo = 0u;
        unsigned hi = __float_as_uint(smx);
        while (hi - lo > 1u) {
            const unsigned mid = (lo + hi) >> 1;
            const float t = __uint_as_float(mid);
            int c = 0;
            #pragma unroll
            for (int j = 0; j < EPT; j++) c += (s_r[j] > t);
            c = blk_cnt(c, redi, lane, warp);
            if (c >= keep_k) lo = mid; else hi = mid;
        }
        thr = __uint_as_float(hi);     // exact reference threshold
    }

    // ---- pause denom: sum(tail_cand * tail) ----
    const float inv_mts = 1e-6f / fmaxf(tc, 1.0f);
    const float itemp   = 1.0f / 0.12f;
    float a_dn = 0.f;
    #pragma unroll
    for (int j = 0; j < EPT; j++) {
        const int i = tid + j * NT;
        const bool pf = (i < F);
        float tcnd = 0.f;
        if (!pf) {
            const float u = sm_um[i];
            const float g = 1.0f / (1.0f + __expf((thr - s_r[j]) * itemp));
            // tail_cand = max(score*gate*um, 0)*tail + (tail/mts)*1e-6, with tail = u here
            tcnd = fmaxf(s_r[j] * g * u, 0.f) * u + u * inv_mts;
            a_dn += tcnd * u;          // * tail
        }
        s_r[j] = tcnd;                 // reuse registers for the epilogue
    }
    const float dn = fmaxf(blk_sum(a_dn, redf, lane, warp), 1e-6f);
    const float scale_p = (tc > 0.f && rem_p > 0.f) ? (rem_p / dn) : 0.f;

    // ---- epilogue: write [2,B,T] ----
    float* out_s = g_out + off;
    float* out_p = g_out + (size_t)B * T_LEN + off;
    #pragma unroll
    for (int j = 0; j < EPT; j++) {
        const int i = tid + j * NT;
        const bool pf = (i < F);
        const float u  = sm_um[i];
        const float av = sm_av[i];
        float sp, pa;
        if (pf) {
            sp = av * u * u;                       // prev_speech*um*prefix, then *um
            pa = sm_pb[i] * u * u;                 // prev_pause *um*prefix, then *um
        } else {
            sp = av * u * scale_s * u * u;         // candidate(c*u)*scale_s*tail(u)*um(u)
            pa = s_r[j] * scale_p * u * u;         // tail_cand*scale_p*tail(u)*um(u)
        }
        out_s[i] = sp;
        out_p[i] = pa;
    }
}

// ---------------- launch ----------------
extern "C" void kernel_launch(void* const* d_in, const int* in_sizes, int n_in,
                              void* d_out, int out_size)
{
    const float* da  = (const float*)d_in[0];
    const float* lr  = (const float*)d_in[1];
    const float* pw  = (const float*)d_in[2];
    const float* bl  = (const float*)d_in[3];
    const float* um  = (const float*)d_in[4];
    const float* sbw = (const float*)d_in[5];
    const float* pbw = (const float*)d_in[6];
    const float* pse = (const float*)d_in[7];
    const float* ppe = (const float*)d_in[8];
    const int*   cf  = (const int*)  d_in[9];
    float* out = (float*)d_out;

    const int B = in_sizes[5];                       // speech_budget_win is [B]
    // keep_k = max(1, round(T * 0.35)) with T = 8192 -> 2867
    int keep_k = (int)(0.35 * (double)T_LEN + 0.5);
    if (keep_k < 1) keep_k = 1;

    const int smem_bytes = 3 * T_LEN * (int)sizeof(float);   // 96 KB dynamic
    cudaFuncSetAttribute(srp_kernel, cudaFuncAttributeMaxDynamicSharedMemorySize, smem_bytes);

    srp_kernel<<<B, NT, smem_bytes>>>(da, lr, pw, bl, um, sbw, pbw, pse, ppe, cf,
                                      out, B, keep_k);
}

// round 2
// speedup vs baseline: 1.5471x; 1.5471x over previous
#include <cuda_runtime.h>
#include <math.h>

#define T_LEN 8192
#define NT    512
#define NV    4                  // float4 chunks per thread (T_LEN/4/NT)
#define EPT   16                 // scalar elements per thread
#define NWARP (NT / 32)          // 16

// ---------------- block reductions ----------------
__device__ __forceinline__ int blk_cnt(int v, volatile int* red, int lane, int warp) {
    #pragma unroll
    for (int o = 16; o > 0; o >>= 1) v += __shfl_xor_sync(0xffffffffu, v, o);
    if (lane == 0) red[warp] = v;
    __syncthreads();
    int t = 0;
    #pragma unroll
    for (int w = 0; w < NWARP; w++) t += red[w];
    __syncthreads();
    return t;
}

__device__ __forceinline__ float blk_sum1(float v, volatile float* red, int lane, int warp) {
    #pragma unroll
    for (int o = 16; o > 0; o >>= 1) v += __shfl_xor_sync(0xffffffffu, v, o);
    if (lane == 0) red[warp] = v;
    __syncthreads();
    float t = 0.f;
    #pragma unroll
    for (int w = 0; w < NWARP; w++) t += red[w];
    __syncthreads();
    return t;
}

// ---------------- main kernel: one CTA per batch row ----------------
__global__ __launch_bounds__(NT, 2)
void srp_kernel(const float* __restrict__ g_da,   // dur_anchor_src      [B,T]
                const float* __restrict__ g_lr,   // dur_logratio_unit   [B,T]
                const float* __restrict__ g_pw,   // pause_weight_unit   [B,T]
                const float* __restrict__ g_bl,   // boundary_latent     [B,T]
                const float* __restrict__ g_um,   // unit_mask           [B,T]
                const float* __restrict__ g_sbw,  // speech_budget_win   [B]
                const float* __restrict__ g_pbw,  // pause_budget_win    [B]
                const float* __restrict__ g_pse,  // previous_speech_exec[B,T]
                const float* __restrict__ g_ppe,  // previous_pause_exec [B,T]
                const int*   __restrict__ g_cf,   // commit_frontier     [B]
                float*       __restrict__ g_out,  // [2,B,T]
                int B, int keep_k)
{
    extern __shared__ float smem[];
    float4* sm_um = (float4*)smem;                    // [T/4] unit_mask
    float4* sm_av = (float4*)(smem + T_LEN);          // [T/4] prefix ? prev_speech : clip-candidate
    float4* sm_pb = (float4*)(smem + 2 * T_LEN);      // [T/4] prefix ? prev_pause  : 0
    __shared__ float redf[NWARP][6];
    __shared__ float redo[6];
    __shared__ int   redi[NWARP];
    __shared__ int   s_cnt;
    __shared__ float s_comp[64];
    __shared__ float s_thr;

    const int b    = blockIdx.x;
    const int tid  = threadIdx.x;
    const int lane = tid & 31;
    const int warp = tid >> 5;
    const size_t off = (size_t)b * T_LEN;

    const float4* da4  = (const float4*)(g_da  + off);
    const float4* lr4  = (const float4*)(g_lr  + off);
    const float4* pw4  = (const float4*)(g_pw  + off);
    const float4* bl4  = (const float4*)(g_bl  + off);
    const float4* um4  = (const float4*)(g_um  + off);
    const float4* pse4 = (const float4*)(g_pse + off);
    const float4* ppe4 = (const float4*)(g_ppe + off);

    const int F = g_cf[b];

    // ---- phase 1: stream inputs once (float4), reductions, cache state ----
    float s_r[EPT];
    float a_ps = 0.f, a_pp = 0.f, a_tc = 0.f, a_cs = 0.f, a_mx = 0.f;
    int   a_c0 = 0;

    #pragma unroll
    for (int j = 0; j < NV; j++) {
        const int c = tid + j * NT;           // float4 chunk index
        const float4 u4 = um4[c];
        const float4 d4 = da4[c];
        const float4 l4 = lr4[c];
        const float4 p4 = pw4[c];
        const float4 b4 = bl4[c];
        const float4 s4 = pse4[c];
        const float4 q4 = ppe4[c];
        float4 av, pb;
        const int ibase = 4 * c;

#define PROC(E, CMP) {                                                          \
        const float u      = u4.CMP;                                            \
        const float anchor = fmaxf(d4.CMP, 1.0f);                               \
        const float cnd    = fminf(fmaxf(anchor * __expf(l4.CMP), 1.0f),        \
                                   anchor * 3.0f);                              \
        const float sc     = (fmaxf(p4.CMP, 0.f)                                \
                              + 0.15f * (0.1f + fmaxf(b4.CMP, 0.f))) * u;       \
        const bool  pf     = (ibase + E) < F;                                   \
        const float tail   = pf ? 0.f : u;                                      \
        if (pf) { a_ps += s4.CMP * u; a_pp += q4.CMP * u; }                     \
        a_tc += tail;                                                           \
        a_cs += cnd * u * tail;                                                 \
        a_mx  = fmaxf(a_mx, sc);                                                \
        a_c0 += (sc > 0.f);                                                     \
        s_r[4 * j + E] = sc;                                                    \
        av.CMP = pf ? s4.CMP : cnd;                                             \
        pb.CMP = pf ? q4.CMP : 0.f; }

        PROC(0, x) PROC(1, y) PROC(2, z) PROC(3, w)
#undef PROC
        sm_um[c] = u4;
        sm_av[c] = av;
        sm_pb[c] = pb;
    }

    // ---- fused 6-way block reduction (4 sums, 1 max, 1 exact int count) ----
    {
        float v0 = a_ps, v1 = a_pp, v2 = a_tc, v3 = a_cs, v4 = a_mx, v5 = (float)a_c0;
        #pragma unroll
        for (int o = 16; o > 0; o >>= 1) {
            v0 += __shfl_xor_sync(0xffffffffu, v0, o);
            v1 += __shfl_xor_sync(0xffffffffu, v1, o);
            v2 += __shfl_xor_sync(0xffffffffu, v2, o);
            v3 += __shfl_xor_sync(0xffffffffu, v3, o);
            v4  = fmaxf(v4, __shfl_xor_sync(0xffffffffu, v4, o));
            v5 += __shfl_xor_sync(0xffffffffu, v5, o);
        }
        if (lane == 0) {
            redf[warp][0] = v0; redf[warp][1] = v1; redf[warp][2] = v2;
            redf[warp][3] = v3; redf[warp][4] = v4; redf[warp][5] = v5;
        }
        __syncthreads();
        if (warp == 0) {
            float w0 = (lane < NWARP) ? redf[lane][0] : 0.f;
            float w1 = (lane < NWARP) ? redf[lane][1] : 0.f;
            float w2 = (lane < NWARP) ? redf[lane][2] : 0.f;
            float w3 = (lane < NWARP) ? redf[lane][3] : 0.f;
            float w4 = (lane < NWARP) ? redf[lane][4] : 0.f;  // scores >= 0
            float w5 = (lane < NWARP) ? redf[lane][5] : 0.f;
            #pragma unroll
            for (int o = 8; o > 0; o >>= 1) {
                w0 += __shfl_xor_sync(0xffffffffu, w0, o);
                w1 += __shfl_xor_sync(0xffffffffu, w1, o);
                w2 += __shfl_xor_sync(0xffffffffu, w2, o);
                w3 += __shfl_xor_sync(0xffffffffu, w3, o);
                w4  = fmaxf(w4, __shfl_xor_sync(0xffffffffu, w4, o));
                w5 += __shfl_xor_sync(0xffffffffu, w5, o);
            }
            if (lane == 0) {
                redo[0] = w0; redo[1] = w1; redo[2] = w2;
                redo[3] = w3; redo[4] = w4; redo[5] = w5;
            }
        }
        __syncthreads();
    }
    const float ps  = redo[0];
    const float pp  = redo[1];
    const float tc  = redo[2];
    const float cs  = redo[3];
    const float smx = redo[4];
    const int   c0  = (int)redo[5];

    // ---- per-row scalars ----
    const float sbud    = fmaxf(__ldg(g_sbw + b), ps + tc * 1.0f);   // MIN_SPEECH = 1.0
    const float pbud    = fmaxf(__ldg(g_pbw + b), pp);
    const float rem_s   = sbud - ps;
    const float cts     = fmaxf(cs, 1e-6f);
    const float scale_s = (tc > 0.f && rem_s > 0.f) ? (rem_s / cts) : 0.f;
    const float rem_p   = fmaxf(pbud - pp, 0.f);

    // ---- exact k-th-largest: value-guided bisection + warp-0 ballot finish ----
    float thr = 0.f;
    if (c0 >= keep_k) {
        // invariant: count(> lo) = c_lo >= k, count(> hi) = c_hi < k
        unsigned lo_b = 0u, hi_b = __float_as_uint(smx);
        float lo_f = 0.f, hi_f = smx;
        int c_lo = c0, c_hi = 0;

        while (hi_b - lo_b > 1u && (c_lo - c_hi) > 32) {
            // value-space midpoint, clamped strictly inside the bit bracket
            unsigned mid_b = __float_as_uint(0.5f * (lo_f + hi_f));
            if (mid_b <= lo_b) mid_b = lo_b + 1u;
            else if (mid_b >= hi_b) mid_b = hi_b - 1u;
            const float mid_f = __uint_as_float(mid_b);

            int cl = 0;
            #pragma unroll
            for (int j = 0; j < EPT; j++) cl += (s_r[j] > mid_f);
            cl = blk_cnt(cl, redi, lane, warp);

            if (cl >= keep_k) { lo_b = mid_b; lo_f = mid_f; c_lo = cl; }
            else              { hi_b = mid_b; hi_f = mid_f; c_hi = cl; }
        }

        if (hi_b - lo_b == 1u) {
            thr = hi_f;                       // exact
        } else {
            // compact the <=32 in-bracket elements, finish on warp 0 (no barriers)
            if (tid == 0) s_cnt = 0;
            __syncthreads();
            #pragma unroll
            for (int j = 0; j < EPT; j++) {
                const float x = s_r[j];
                if (x > lo_f && x <= hi_f) {
                    int p = atomicAdd(&s_cnt, 1);
                    if (p < 64) s_comp[p] = x;
                }
            }
            __syncthreads();
            if (warp == 0) {
                const int m  = s_cnt;
                const int kk = keep_k - c_hi;             // rank within bracket
                const float x = (lane < m) ? s_comp[lane] : -1.f;
                unsigned lb = lo_b, hb = hi_b;
                while (hb - lb > 1u) {
                    const unsigned mb = (lb + hb) >> 1;   // bit midpoint (positive floats)
                    const float mf = __uint_as_float(mb);
                    const int c = __popc(__ballot_sync(0xffffffffu, x > mf));
                    if (c >= kk) lb = mb; else hb = mb;
                }
                if (lane == 0) s_thr = __uint_as_float(hb);
            }
            __syncthreads();
            thr = s_thr;
        }
    }

    // ---- pause denominator ----
    const float inv_mts = 1e-6f / fmaxf(tc, 1.0f);
    const float itemp   = 1.0f / 0.12f;
    float a_dn = 0.f;
    #pragma unroll
    for (int j = 0; j < NV; j++) {
        const int c = tid + j * NT;
        const float4 u4 = sm_um[c];
        const int ibase = 4 * c;
#define PROCD(E, CMP) {                                                         \
        const bool pf = (ibase + E) < F;                                        \
        float tcnd = 0.f;                                                       \
        if (!pf) {                                                              \
            const float u = u4.CMP;                                             \
            const float s = s_r[4 * j + E];                                     \
            const float g = 1.0f / (1.0f + __expf((thr - s) * itemp));          \
            tcnd = fmaxf(s * g * u, 0.f) * u + u * inv_mts;                     \
            a_dn += tcnd * u;                                                   \
        }                                                                       \
        s_r[4 * j + E] = tcnd; }
        PROCD(0, x) PROCD(1, y) PROCD(2, z) PROCD(3, w)
#undef PROCD
    }
    const float dn = fmaxf(blk_sum1(a_dn, (volatile float*)redi /*reuse? no*/ == nullptr ? nullptr : (volatile float*)&redf[0][0], lane, warp), 1e-6f);
    const float scale_p = (tc > 0.f && rem_p > 0.f) ? (rem_p / dn) : 0.f;

    // ---- epilogue: vectorized writes of [2,B,T] ----
    float4* out_s4 = (float4*)(g_out + off);
    float4* out_p4 = (float4*)(g_out + (size_t)B * T_LEN + off);
    #pragma unroll
    for (int j = 0; j < NV; j++) {
        const int c = tid + j * NT;
        const float4 u4 = sm_um[c];
        const float4 av = sm_av[c];
        const float4 pb = sm_pb[c];
        const int ibase = 4 * c;
        float4 os, op;
#define PROCE(E, CMP) {                                                         \
        const bool  pf = (ibase + E) < F;                                       \
        const float u  = u4.CMP;                                                \
        if (pf) { os.CMP = av.CMP * u * u;                                      \
                  op.CMP = pb.CMP * u * u; }                                    \
        else    { os.CMP = av.CMP * scale_s * u * u * u;                        \
                  op.CMP = s_r[4 * j + E] * scale_p * u * u; } }
        PROCE(0, x) PROCE(1, y) PROCE(2, z) PROCE(3, w)
#undef PROCE
        out_s4[c] = os;
        out_p4[c] = op;
    }
}

// ---------------- launch ----------------
extern "C" void kernel_launch(void* const* d_in, const int* in_sizes, int n_in,
                              void* d_out, int out_size)
{
    const float* da  = (const float*)d_in[0];
    const float* lr  = (const float*)d_in[1];
    const float* pw  = (const float*)d_in[2];
    const float* bl  = (const float*)d_in[3];
    const float* um  = (const float*)d_in[4];
    const float* sbw = (const float*)d_in[5];
    const float* pbw = (const float*)d_in[6];
    const float* pse = (const float*)d_in[7];
    const float* ppe = (const float*)d_in[8];
    const int*   cf  = (const int*)  d_in[9];
    float* out = (float*)d_out;

    const int B = in_sizes[5];                       // speech_budget_win is [B]
    int keep_k = (int)(0.35 * (double)T_LEN + 0.5);  // round(T*0.35) = 2867
    if (keep_k < 1) keep_k = 1;

    const int smem_bytes = 3 * T_LEN * (int)sizeof(float);   // 96 KB dynamic
    cudaFuncSetAttribute(srp_kernel, cudaFuncAttributeMaxDynamicSharedMemorySize, smem_bytes);

    srp_kernel<<<B, NT, smem_bytes>>>(da, lr, pw, bl, um, sbw, pbw, pse, ppe, cf,
                                      out, B, keep_k);
}